// round 17
// baseline (speedup 1.0000x reference)
#include <cuda_runtime.h>
#include <math.h>

#define BN   2
#define NPTS 8192
#define KNN  16
#define CIN  32
#define EIN  67      // 32 + 32 + 3
#define HID  128
#define COUT 64
#define TOT  (BN*NPTS)
#define FULLM 0xffffffffu
#define FMAX  3.402823466e38f

// 3-D cell sort for KNN: 16^3 cells, z contiguous (lex order bx,by,bz)
#define NC3    16
#define CELLS3 (NC3*NC3*NC3)     // 4096 per batch
#define XMIN  (-4.65f)
#define XSPAN 9.3f
#define BW3   (XSPAN/NC3)        // 0.58125
#define INVBW3 (NC3/XSPAN)

// Scratch (no allocations allowed)
__device__ int    g_idx[TOT*KNN];
__device__ float  g_mid[TOT*COUT];
__device__ float4 g_vert4[TOT];
__device__ float  g_q[TOT*HID];
__device__ float  g_p[TOT*HID];
__device__ float4 g_stat[TOT];
__device__ int    g_ccnt[BN][CELLS3];
__device__ int    g_cstart[BN][CELLS3+1];
__device__ int    g_ccur[BN][CELLS3];
__device__ float4 g_sx4[TOT];              // cell-sorted points
__device__ int    g_ssid[TOT];             // sorted -> original GLOBAL index

// ---------------------------------------------------------------------------
__global__ void prep_kernel(const float* __restrict__ verts) {
    int i = blockIdx.x * blockDim.x + threadIdx.x;
    if (i < TOT) {
        float x = verts[i*3+0], y = verts[i*3+1], z = verts[i*3+2];
        g_vert4[i] = make_float4(x, y, z, x*x + y*y + z*z);
    }
    if (i < BN*CELLS3) ((int*)g_ccnt)[i] = 0;
}

__device__ __forceinline__ int clampi(int v, int lo, int hi) {
    return v < lo ? lo : (v > hi ? hi : v);
}

__global__ void bin_kernel() {
    int i = blockIdx.x * blockDim.x + threadIdx.x;
    if (i >= TOT) return;
    float4 v = g_vert4[i];
    int bx = clampi((int)((v.x - XMIN) * INVBW3), 0, NC3-1);
    int by = clampi((int)((v.y - XMIN) * INVBW3), 0, NC3-1);
    int bz = clampi((int)((v.z - XMIN) * INVBW3), 0, NC3-1);
    atomicAdd(&g_ccnt[i >> 13][(bx*NC3 + by)*NC3 + bz], 1);
}

// One block per batch, 1024 threads, 4 cells/thread + block-wide scan.
__global__ void scan_kernel() {
    __shared__ int s[1024];
    int bb = blockIdx.x, t = threadIdx.x;
    int lo = t*4;
    int loc[4]; int sum = 0;
#pragma unroll
    for (int k = 0; k < 4; k++) { loc[k] = g_ccnt[bb][lo+k]; sum += loc[k]; }
    s[t] = sum;
    __syncthreads();
    for (int d = 1; d < 1024; d <<= 1) {
        int u = (t >= d) ? s[t-d] : 0;
        __syncthreads();
        s[t] += u;
        __syncthreads();
    }
    int run = s[t] - sum;
#pragma unroll
    for (int k = 0; k < 4; k++) {
        g_cstart[bb][lo+k] = run;
        g_ccur[bb][lo+k]   = run;
        run += loc[k];
    }
    if (t == 1023) g_cstart[bb][CELLS3] = NPTS;
}

__global__ void scatter_kernel() {
    int i = blockIdx.x * blockDim.x + threadIdx.x;
    if (i >= TOT) return;
    float4 v = g_vert4[i];
    int bb = i >> 13;
    int bx = clampi((int)((v.x - XMIN) * INVBW3), 0, NC3-1);
    int by = clampi((int)((v.y - XMIN) * INVBW3), 0, NC3-1);
    int bz = clampi((int)((v.z - XMIN) * INVBW3), 0, NC3-1);
    int slot = bb * NPTS + atomicAdd(&g_ccur[bb][(bx*NC3 + by)*NC3 + bz], 1);
    g_sx4[slot]  = v;
    g_ssid[slot] = i;
}

// ---------------------------------------------------------------------------
__device__ __forceinline__ void scan_seg(int a, int b, int sbase, float4 qv,
                                         int lane, float& key, int& idx) {
    for (int i = a; i < b; i += 32) {
        int j = i + lane;
        float d = FMAX;
        if (j < b) {
            float4 c = __ldg(&g_sx4[sbase + j]);
            float dot = fmaf(qv.x, c.x, fmaf(qv.y, c.y, qv.z*c.z));
            d = fmaf(-2.0f, dot, qv.w + c.w);
        }
        float thb = __shfl_sync(FULLM, key, 15);
        unsigned mask = __ballot_sync(FULLM, d < thb);
        while (mask) {
            int src = __ffs(mask) - 1;
            mask &= mask - 1;
            float v  = __shfl_sync(FULLM, d, src);
            int   vi = i + src;
            float pk = __shfl_up_sync(FULLM, key, 1);
            int   pi = __shfl_up_sync(FULLM, idx, 1);
            if (v < key) {
                if (lane > 0 && v < pk) { key = pk; idx = pi; }
                else                    { key = v;  idx = vi; }
            }
        }
    }
}

// ---------------------------------------------------------------------------
// KNN: 512 blocks x 8 warps x 4 queries. CSR staged in SMEM ONCE per block
// (32 consecutive queries share one batch; 8192 % 32 == 0). Per-query search
// identical to the proven R16 version: center-cell start, bitonic warm-up,
// face-wise expansion, exact covering stop bound.
// ---------------------------------------------------------------------------
__global__ void __launch_bounds__(256) knn_kernel() {
    __shared__ int scs[CELLS3+1];    // 16.4KB
    int tid  = threadIdx.x;
    int lane = tid & 31;
    int w    = tid >> 5;
    int qbase = blockIdx.x * 32;
    int bb    = qbase >> 13;
    int sbase = bb * NPTS;

    for (int i = tid; i <= CELLS3; i += 256) scs[i] = g_cstart[bb][i];
    __syncthreads();

    for (int r = 0; r < 4; r++) {
        int gq = qbase + w*4 + r;

        float4 qv = g_vert4[gq];
        int bx0 = clampi((int)((qv.x - XMIN) * INVBW3), 0, NC3-1);
        int by0 = clampi((int)((qv.y - XMIN) * INVBW3), 0, NC3-1);
        int bz0 = clampi((int)((qv.z - XMIN) * INVBW3), 0, NC3-1);

        int xlo = bx0, xhi = bx0;
        int ylo = by0, yhi = by0;
        int zlo = bz0, zhi = bz0;

        // bitonic warm-start: first 32 of the center cell
        int cb0 = (bx0*NC3 + by0)*NC3;
        int a0 = scs[cb0 + bz0], b0 = scs[cb0 + bz0 + 1];
        float key; int idx;
        {
            float d = FMAX; int vi = 0;
            int j = a0 + lane;
            if (j < b0) {
                float4 c = __ldg(&g_sx4[sbase + j]);
                float dot = fmaf(qv.x, c.x, fmaf(qv.y, c.y, qv.z*c.z));
                d = fmaf(-2.0f, dot, qv.w + c.w);
                vi = j;
            }
#pragma unroll
            for (int k = 2; k <= 32; k <<= 1) {
#pragma unroll
                for (int s = k >> 1; s > 0; s >>= 1) {
                    int partner = lane ^ s;
                    float ok = __shfl_xor_sync(FULLM, d,  s);
                    int   oi = __shfl_xor_sync(FULLM, vi, s);
                    bool dir = ((lane & k) == 0);
                    bool otherLess = (ok < d) || (ok == d && partner < lane);
                    bool lower = ((lane & s) == 0);
                    bool take = (lower == dir) ? otherLess : !otherLess;
                    if (take) { d = ok; vi = oi; }
                }
            }
            key = d; idx = vi;
        }
        scan_seg(min(a0 + 32, b0), b0, sbase, qv, lane, key, idx);

        for (;;) {
            float gxl = (xlo == 0)       ? FMAX : qv.x - (XMIN + xlo * BW3);
            float gxh = (xhi == NC3 - 1) ? FMAX : (XMIN + (xhi + 1) * BW3) - qv.x;
            float gyl = (ylo == 0)       ? FMAX : qv.y - (XMIN + ylo * BW3);
            float gyh = (yhi == NC3 - 1) ? FMAX : (XMIN + (yhi + 1) * BW3) - qv.y;
            float gzl = (zlo == 0)       ? FMAX : qv.z - (XMIN + zlo * BW3);
            float gzh = (zhi == NC3 - 1) ? FMAX : (XMIN + (zhi + 1) * BW3) - qv.z;
            float bnd = fminf(fminf(fminf(gxl, gxh), fminf(gyl, gyh)), fminf(gzl, gzh));
            if (bnd > 1e37f) break;
            float th = __shfl_sync(FULLM, key, 15);
            if (th <= bnd * bnd) break;

            if (gxl <= gxh && gxl <= gyl && gxl <= gyh && gxl <= gzl && gxl <= gzh) {
                xlo--;
                for (int by = ylo; by <= yhi; by++) {
                    int cb = (xlo*NC3 + by)*NC3;
                    scan_seg(scs[cb + zlo], scs[cb + zhi + 1], sbase, qv, lane, key, idx);
                }
            } else if (gxh <= gyl && gxh <= gyh && gxh <= gzl && gxh <= gzh) {
                xhi++;
                for (int by = ylo; by <= yhi; by++) {
                    int cb = (xhi*NC3 + by)*NC3;
                    scan_seg(scs[cb + zlo], scs[cb + zhi + 1], sbase, qv, lane, key, idx);
                }
            } else if (gyl <= gyh && gyl <= gzl && gyl <= gzh) {
                ylo--;
                for (int bx = xlo; bx <= xhi; bx++) {
                    int cb = (bx*NC3 + ylo)*NC3;
                    scan_seg(scs[cb + zlo], scs[cb + zhi + 1], sbase, qv, lane, key, idx);
                }
            } else if (gyh <= gzl && gyh <= gzh) {
                yhi++;
                for (int bx = xlo; bx <= xhi; bx++) {
                    int cb = (bx*NC3 + yhi)*NC3;
                    scan_seg(scs[cb + zlo], scs[cb + zhi + 1], sbase, qv, lane, key, idx);
                }
            } else if (gzl <= gzh) {
                zlo--;
                for (int bx = xlo; bx <= xhi; bx++)
                    for (int by = ylo; by <= yhi; by++) {
                        int cb = (bx*NC3 + by)*NC3;
                        scan_seg(scs[cb + zlo], scs[cb + zlo + 1], sbase, qv, lane, key, idx);
                    }
            } else {
                zhi++;
                for (int bx = xlo; bx <= xhi; bx++)
                    for (int by = ylo; by <= yhi; by++) {
                        int cb = (bx*NC3 + by)*NC3;
                        scan_seg(scs[cb + zhi], scs[cb + zhi + 1], sbase, qv, lane, key, idx);
                    }
            }
        }

        if (lane < KNN) g_idx[gq*KNN + lane] = g_ssid[sbase + idx];
    }
}

// ---------------------------------------------------------------------------
// Precompute Q, P, stats: 512 blocks x 8 warps x 4 points; W1 filled once.
// ---------------------------------------------------------------------------
__global__ void __launch_bounds__(256) precomp_kernel(
    const float* __restrict__ verts, const float* __restrict__ feat,
    const float* __restrict__ W1, const float* __restrict__ b1)
{
    __shared__ float sW1[EIN*HID];   // 34.3KB
    int tid = threadIdx.x, lane = tid & 31, w = tid >> 5;
    for (int e = tid; e < EIN*HID; e += 256) sW1[e] = W1[e];
    __syncthreads();

    int c = lane*4;
    for (int r = 0; r < 4; r++) {
        int p = blockIdx.x * 32 + w*4 + r;
        float4 f4 = make_float4(0.f,0.f,0.f,0.f);
        if (lane < 8) f4 = *(const float4*)&feat[p*CIN + lane*4];
        float vx = verts[p*3+0], vy = verts[p*3+1], vz = verts[p*3+2];

        float4 q  = make_float4(0.f,0.f,0.f,0.f);
        float4 pp = *(const float4*)&b1[c];

#pragma unroll
        for (int src = 0; src < 8; src++) {
            float fx = __shfl_sync(FULLM, f4.x, src);
            float fy = __shfl_sync(FULLM, f4.y, src);
            float fz = __shfl_sync(FULLM, f4.z, src);
            float fw = __shfl_sync(FULLM, f4.w, src);
            float fv[4] = {fx, fy, fz, fw};
            int k0 = src*4;
#pragma unroll
            for (int kk = 0; kk < 4; kk++) {
                int k = k0 + kk;
                float4 wa = *(const float4*)&sW1[k*HID + c];
                float4 wb = *(const float4*)&sW1[(CIN + k)*HID + c];
                q.x  = fmaf(fv[kk], wa.x, q.x);  q.y  = fmaf(fv[kk], wa.y, q.y);
                q.z  = fmaf(fv[kk], wa.z, q.z);  q.w  = fmaf(fv[kk], wa.w, q.w);
                pp.x = fmaf(fv[kk], wb.x, pp.x); pp.y = fmaf(fv[kk], wb.y, pp.y);
                pp.z = fmaf(fv[kk], wb.z, pp.z); pp.w = fmaf(fv[kk], wb.w, pp.w);
            }
        }
        float vv[3] = {vx, vy, vz};
#pragma unroll
        for (int k = 0; k < 3; k++) {
            float4 wc = *(const float4*)&sW1[(2*CIN + k)*HID + c];
            q.x  = fmaf(vv[k],  wc.x, q.x);  q.y  = fmaf(vv[k],  wc.y, q.y);
            q.z  = fmaf(vv[k],  wc.z, q.z);  q.w  = fmaf(vv[k],  wc.w, q.w);
            pp.x = fmaf(-vv[k], wc.x, pp.x); pp.y = fmaf(-vv[k], wc.y, pp.y);
            pp.z = fmaf(-vv[k], wc.z, pp.z); pp.w = fmaf(-vv[k], wc.w, pp.w);
        }
        *(float4*)&g_q[p*HID + c] = q;
        *(float4*)&g_p[p*HID + c] = pp;

        float sq  = (q.x + q.y) + (q.z + q.w);
        float sq2 = fmaf(q.x,q.x, fmaf(q.y,q.y, fmaf(q.z,q.z, q.w*q.w)));
        float sp  = (pp.x + pp.y) + (pp.z + pp.w);
        float sp2 = fmaf(pp.x,pp.x, fmaf(pp.y,pp.y, fmaf(pp.z,pp.z, pp.w*pp.w)));
#pragma unroll
        for (int off = 16; off; off >>= 1) {
            sq  += __shfl_xor_sync(FULLM, sq,  off);
            sq2 += __shfl_xor_sync(FULLM, sq2, off);
            sp  += __shfl_xor_sync(FULLM, sp,  off);
            sp2 += __shfl_xor_sync(FULLM, sp2, off);
        }
        if (lane == 0) g_stat[p] = make_float4(sq, sq2, sp, sp2);
    }
}

// ---------------------------------------------------------------------------
__device__ __forceinline__ float gelu_fast(float x) {
    float z2 = 1.5957691216057308f * fmaf(0.044715f * x * x, x, x);
    float e  = __expf(z2);
    float r  = __fdividef(1.0f, e + 1.0f);
    return x - x * r;
}

// ---------------------------------------------------------------------------
// Edge kernel: 512 blocks x 8 warps x 4 points; W2 filled once per block.
// ---------------------------------------------------------------------------
__global__ void __launch_bounds__(256) edge_kernel(
    const float* __restrict__ g1, const float* __restrict__ be1,
    const float* __restrict__ W2, const float* __restrict__ b2)
{
    __shared__ float sW2[HID*COUT];   // 32KB
    __shared__ float sGa[8][HID];     // 4KB
    int tid = threadIdx.x, lane = tid & 31, w = tid >> 5;
    for (int e = tid; e < HID*COUT; e += 256) sW2[e] = W2[e];
    __syncthreads();

    int c = lane * 4;
    float4 g1v = *(const float4*)&g1[c];
    float4 bev = *(const float4*)&be1[c];
    float2 b2v = *(const float2*)&b2[2*lane];

    for (int rr = 0; rr < 4; rr++) {
        int p = blockIdx.x * 32 + w*4 + rr;
        int myidx = (lane < KNN) ? g_idx[p*KNN + lane] : 0;

        float4 P4  = *(const float4*)&g_p[p*HID + c];
        float4 stP = g_stat[p];
        float4 stN = __ldg(&g_stat[myidx]);
        float sumn = stN.x + stP.z;
        float bsqn = stN.y + stP.w;

        float4 accG = make_float4(0.f,0.f,0.f,0.f);

        float4 qn[4];
#pragma unroll
        for (int r = 0; r < 4; r++) {
            int nb = __shfl_sync(FULLM, myidx, r);
            qn[r] = __ldg((const float4*)&g_q[nb*HID + c]);
        }

#pragma unroll
        for (int n = 0; n < KNN; n += 4) {
            float4 h[4];
            float dp[4];
#pragma unroll
            for (int r = 0; r < 4; r++) {
                h[r].x = qn[r].x + P4.x; h[r].y = qn[r].y + P4.y;
                h[r].z = qn[r].z + P4.z; h[r].w = qn[r].w + P4.w;
                dp[r] = fmaf(qn[r].x,P4.x, fmaf(qn[r].y,P4.y, fmaf(qn[r].z,P4.z, qn[r].w*P4.w)));
            }
            if (n + 4 < KNN) {
#pragma unroll
                for (int r = 0; r < 4; r++) {
                    int nb = __shfl_sync(FULLM, myidx, n + 4 + r);
                    qn[r] = __ldg((const float4*)&g_q[nb*HID + c]);
                }
            }
#pragma unroll
            for (int off = 16; off; off >>= 1) {
#pragma unroll
                for (int r = 0; r < 4; r++)
                    dp[r] += __shfl_xor_sync(FULLM, dp[r], off);
            }
#pragma unroll
            for (int r = 0; r < 4; r++) {
                float sum = __shfl_sync(FULLM, sumn, n + r);
                float bsq = __shfl_sync(FULLM, bsqn, n + r);
                float mu  = sum * (1.f/HID);
                float e2  = fmaf(2.0f, dp[r], bsq) * (1.f/HID);
                float rs  = rsqrtf(e2 - mu*mu + 1e-5f);
                accG.x += gelu_fast(fmaf((h[r].x - mu)*rs, g1v.x, bev.x));
                accG.y += gelu_fast(fmaf((h[r].y - mu)*rs, g1v.y, bev.y));
                accG.z += gelu_fast(fmaf((h[r].z - mu)*rs, g1v.z, bev.z));
                accG.w += gelu_fast(fmaf((h[r].w - mu)*rs, g1v.w, bev.w));
            }
        }
        accG.x *= (1.f/KNN); accG.y *= (1.f/KNN);
        accG.z *= (1.f/KNN); accG.w *= (1.f/KNN);

        // stage accG in smem; lane handles output cols 2*lane, 2*lane+1
        __syncwarp();
        *(float4*)&sGa[w][c] = accG;
        __syncwarp();

        float m0 = b2v.x, m1 = b2v.y;
        const float* gw = sGa[w];
#pragma unroll 4
        for (int k0 = 0; k0 < HID; k0 += 4) {
            float4 g4 = *(const float4*)&gw[k0];
            float2 w0 = *(const float2*)&sW2[(k0+0)*COUT + 2*lane];
            float2 w1 = *(const float2*)&sW2[(k0+1)*COUT + 2*lane];
            float2 w2 = *(const float2*)&sW2[(k0+2)*COUT + 2*lane];
            float2 w3 = *(const float2*)&sW2[(k0+3)*COUT + 2*lane];
            m0 = fmaf(g4.x, w0.x, m0); m1 = fmaf(g4.x, w0.y, m1);
            m0 = fmaf(g4.y, w1.x, m0); m1 = fmaf(g4.y, w1.y, m1);
            m0 = fmaf(g4.z, w2.x, m0); m1 = fmaf(g4.z, w2.y, m1);
            m0 = fmaf(g4.w, w3.x, m0); m1 = fmaf(g4.w, w3.y, m1);
        }
        *(float2*)&g_mid[p*COUT + 2*lane] = make_float2(m0, m1);
    }
}

// ---------------------------------------------------------------------------
// MLP2 fused: 64 points per block, grid 256.
// ---------------------------------------------------------------------------
#define M2PTS 64
#define SMEM2_FLOATS (COUT*M2PTS + COUT*HID + HID*COUT)  // 20480

__global__ void __launch_bounds__(256, 2) mlp2_kernel(
    const float* __restrict__ Wo1, const float* __restrict__ bo1,
    const float* __restrict__ go,  const float* __restrict__ beo,
    const float* __restrict__ Wo2, const float* __restrict__ bo2,
    float* __restrict__ out)
{
    extern __shared__ float sm[];
    float* sAt  = sm;
    float* sWo1 = sm + COUT*M2PTS;
    float* sH   = sm;                          // aliases sAt+sWo1
    float* sWo2 = sm + COUT*M2PTS + COUT*HID;

    int tid = threadIdx.x;
    int r0  = blockIdx.x * M2PTS;

    for (int e = tid; e < COUT*HID; e += 256) sWo1[e] = Wo1[e];
    for (int e = tid; e < HID*COUT; e += 256) sWo2[e] = Wo2[e];
    for (int e = tid; e < COUT*M2PTS; e += 256) {
        int r = e & (M2PTS-1), k = e >> 6;
        sAt[k*M2PTS + r] = g_mid[(r0 + r)*COUT + k];
    }
    __syncthreads();

    int tx = tid & 15, ty = tid >> 4;

    float acc[4][8];
#pragma unroll
    for (int i = 0; i < 4; i++)
#pragma unroll
        for (int j = 0; j < 8; j++) acc[i][j] = 0.f;

    for (int k = 0; k < COUT; k++) {
        float4 a4 = *(const float4*)&sAt[k*M2PTS + ty*4];
        float4 c0 = *(const float4*)&sWo1[k*HID + tx*8];
        float4 c1 = *(const float4*)&sWo1[k*HID + tx*8 + 4];
        float a[4] = {a4.x,a4.y,a4.z,a4.w};
        float wv[8] = {c0.x,c0.y,c0.z,c0.w,c1.x,c1.y,c1.z,c1.w};
#pragma unroll
        for (int i = 0; i < 4; i++)
#pragma unroll
            for (int j = 0; j < 8; j++)
                acc[i][j] = fmaf(a[i], wv[j], acc[i][j]);
    }

    __syncthreads();

    float b1j[8], gj[8], bej[8];
#pragma unroll
    for (int j = 0; j < 8; j++) {
        int col = tx*8 + j;
        b1j[j] = bo1[col]; gj[j] = go[col]; bej[j] = beo[col];
    }
#pragma unroll
    for (int i = 0; i < 4; i++) {
        float ps = 0.f, ps2 = 0.f;
#pragma unroll
        for (int j = 0; j < 8; j++) {
            float h = acc[i][j] + b1j[j];
            acc[i][j] = h;
            ps += h; ps2 = fmaf(h, h, ps2);
        }
#pragma unroll
        for (int off = 8; off; off >>= 1) {
            ps  += __shfl_xor_sync(FULLM, ps,  off);
            ps2 += __shfl_xor_sync(FULLM, ps2, off);
        }
        float mu  = ps  * (1.f/HID);
        float var = ps2 * (1.f/HID) - mu*mu;
        float rs  = rsqrtf(var + 1e-5f);
        float o[8];
#pragma unroll
        for (int j = 0; j < 8; j++)
            o[j] = gelu_fast(fmaf((acc[i][j] - mu)*rs, gj[j], bej[j]));
        int row = ty*4 + i;
        *(float4*)&sH[row*132 + tx*8]     = make_float4(o[0],o[1],o[2],o[3]);
        *(float4*)&sH[row*132 + tx*8 + 4] = make_float4(o[4],o[5],o[6],o[7]);
    }
    __syncthreads();

    float acc2[4][4];
#pragma unroll
    for (int i = 0; i < 4; i++)
#pragma unroll
        for (int j = 0; j < 4; j++) acc2[i][j] = 0.f;

    for (int k = 0; k < HID; k += 4) {
        float4 w0 = *(const float4*)&sWo2[(k+0)*COUT + tx*4];
        float4 w1 = *(const float4*)&sWo2[(k+1)*COUT + tx*4];
        float4 w2 = *(const float4*)&sWo2[(k+2)*COUT + tx*4];
        float4 w3 = *(const float4*)&sWo2[(k+3)*COUT + tx*4];
#pragma unroll
        for (int i = 0; i < 4; i++) {
            float4 av = *(const float4*)&sH[(ty*4+i)*132 + k];
            acc2[i][0] = fmaf(av.x, w0.x, fmaf(av.y, w1.x, fmaf(av.z, w2.x, fmaf(av.w, w3.x, acc2[i][0]))));
            acc2[i][1] = fmaf(av.x, w0.y, fmaf(av.y, w1.y, fmaf(av.z, w2.y, fmaf(av.w, w3.y, acc2[i][1]))));
            acc2[i][2] = fmaf(av.x, w0.z, fmaf(av.y, w1.z, fmaf(av.z, w2.z, fmaf(av.w, w3.z, acc2[i][2]))));
            acc2[i][3] = fmaf(av.x, w0.w, fmaf(av.y, w1.w, fmaf(av.z, w2.w, fmaf(av.w, w3.w, acc2[i][3]))));
        }
    }

    float b2j[4];
#pragma unroll
    for (int j = 0; j < 4; j++) b2j[j] = bo2[tx*4 + j];
#pragma unroll
    for (int i = 0; i < 4; i++) {
        int row = r0 + ty*4 + i;
#pragma unroll
        for (int j = 0; j < 4; j++)
            out[row*COUT + tx*4 + j] = acc2[i][j] + b2j[j];
    }
}

// ---------------------------------------------------------------------------
extern "C" void kernel_launch(void* const* d_in, const int* in_sizes, int n_in,
                              void* d_out, int out_size) {
    const float* verts = (const float*)d_in[0];
    const float* feat  = (const float*)d_in[1];
    const float* W1    = (const float*)d_in[2];
    const float* b1    = (const float*)d_in[3];
    const float* g1    = (const float*)d_in[4];
    const float* be1   = (const float*)d_in[5];
    const float* W2    = (const float*)d_in[6];
    const float* b2    = (const float*)d_in[7];
    const float* Wo1   = (const float*)d_in[8];
    const float* bo1   = (const float*)d_in[9];
    const float* go    = (const float*)d_in[10];
    const float* beo   = (const float*)d_in[11];
    const float* Wo2   = (const float*)d_in[12];
    const float* bo2   = (const float*)d_in[13];
    float* out = (float*)d_out;

    const int smem2 = SMEM2_FLOATS * 4;   // 81920
    cudaFuncSetAttribute(mlp2_kernel, cudaFuncAttributeMaxDynamicSharedMemorySize, smem2);

    prep_kernel<<<(TOT + 255)/256, 256>>>(verts);
    bin_kernel<<<(TOT + 255)/256, 256>>>();
    scan_kernel<<<BN, 1024>>>();
    scatter_kernel<<<(TOT + 255)/256, 256>>>();
    knn_kernel<<<TOT/32, 256>>>();                       // 512 blocks, 4 q/warp
    precomp_kernel<<<TOT/32, 256>>>(verts, feat, W1, b1);
    edge_kernel<<<TOT/32, 256>>>(g1, be1, W2, b2);
    mlp2_kernel<<<TOT/M2PTS, 256, smem2>>>(Wo1, bo1, go, beo, Wo2, bo2, out);
}